// round 8
// baseline (speedup 1.0000x reference)
#include <cuda_runtime.h>

#define TS   32          // output tile (TS x TS)
#define HALO 5
#define IN   42          // TS + 2*HALO
#define SXYS 46          // sXY row stride in float2 units (bank-conflict-free)
#define HS   34          // h-array row stride in float2 units
#define IMH  512
#define IMW  512
#define NPLANES (32*3)
#define NPIX    ((long long)NPLANES * IMH * IMW)   // 25165824

typedef unsigned long long u64;

// Normalized 11-tap Gaussian (sigma=1.5), compile-time so taps become FFMA-imm.
__device__ constexpr float GW[11] = {
    0.00102838f, 0.00759876f, 0.03600077f, 0.10936071f, 0.21300550f,
    0.26601172f,
    0.21300550f, 0.10936071f, 0.03600077f, 0.00759876f, 0.00102838f
};

// [0] = sum |x-y|, [1] = sum ssim_map. Zero-initialized at module load;
// finalize_kernel resets them after reading, so every replay starts from 0.
__device__ double g_acc[2] = {0.0, 0.0};

__device__ __forceinline__ u64 pack2(float lo, float hi) {
    u64 r; asm("mov.b64 %0, {%1, %2};" : "=l"(r) : "f"(lo), "f"(hi)); return r;
}
__device__ __forceinline__ void unpack2(u64 v, float& lo, float& hi) {
    asm("mov.b64 {%0, %1}, %2;" : "=f"(lo), "=f"(hi) : "l"(v));
}
__device__ __forceinline__ void fma2(u64& acc, u64 a, u64 b) {
    asm("fma.rn.f32x2 %0, %1, %2, %0;" : "+l"(acc) : "l"(a), "l"(b));
}

__global__ __launch_bounds__(256, 4) void ssim_l1_kernel(
    const float* __restrict__ pred, const float* __restrict__ tgt)
{
    extern __shared__ float smf[];
    u64* sXY = reinterpret_cast<u64*>(smf);   // IN*SXYS pairs (x,y)
    u64* hXY = sXY + IN * SXYS;               // IN*HS pairs (E_h[x], E_h[y])
    u64* hPQ = hXY + IN * HS;                 // IN*HS pairs (E_h[p], E_h[q])
    u64* w2s = hPQ + IN * HS;                 // 11 packed (w,w) + pad
    float* red = smf;                         // reduction scratch (reuse)

    const int tid = threadIdx.x;
    const int plane = blockIdx.z;
    const float* __restrict__ px = pred + (size_t)plane * (IMH * IMW);
    const float* __restrict__ py = tgt  + (size_t)plane * (IMH * IMW);
    const int bx0 = blockIdx.x * TS - HALO;
    const int by0 = blockIdx.y * TS - HALO;

    if (tid < 11) w2s[tid] = pack2(GW[tid], GW[tid]);

    // ---- Phase 1: load halo tile, interleaved (x,y); fold L1 for interior
    //      pixels (each image pixel is interior of exactly one tile).
    float l1 = 0.f;
    for (int i = tid; i < IN * IN; i += 256) {
        int r = i / IN;
        int c = i - r * IN;
        int gy = by0 + r, gx = bx0 + c;
        float x = 0.f, y = 0.f;
        if ((unsigned)gy < IMH && (unsigned)gx < IMW) {
            int o = gy * IMW + gx;
            x = px[o];
            y = py[o];
        }
        sXY[r * SXYS + c] = pack2(x, y);
        if (r >= HALO && r < IN - HALO && c >= HALO && c < IN - HALO)
            l1 += fabsf(x - y);
    }
    __syncthreads();   // also publishes w2s

    // ---- Phase 2: horizontal pass with packed pairs. 42 rows x 8 col-groups.
    //      Row-per-lane mapping + stride SXYS=46 keeps LDS.128 conflict-free.
    for (int i = tid; i < IN * (TS / 4); i += 256) {
        int g  = i / IN;          // col-group 0..7
        int r  = i - g * IN;      // row 0..41
        int c0 = g * 4;

        u64 v[16];
        {
            const ulonglong2* p = reinterpret_cast<const ulonglong2*>(sXY + r * SXYS + c0);
#pragma unroll
            for (int j = 0; j < 8; j++) { ulonglong2 t = p[j]; v[2*j] = t.x; v[2*j+1] = t.y; }
        }

        // conv (x,y) pair
        {
            u64 a0 = 0ull, a1 = 0ull, a2 = 0ull, a3 = 0ull;
#pragma unroll
            for (int k = 0; k < 11; k++) {
                u64 w = w2s[k];
                fma2(a0, w, v[k]);
                fma2(a1, w, v[k + 1]);
                fma2(a2, w, v[k + 2]);
                fma2(a3, w, v[k + 3]);
            }
            ulonglong2* o = reinterpret_cast<ulonglong2*>(hXY + r * HS + c0);
            o[0] = make_ulonglong2(a0, a1);
            o[1] = make_ulonglong2(a2, a3);
        }

        // transform window in place: (x,y) -> (p,q) = (x^2+y^2, x*y)
#pragma unroll
        for (int j = 0; j < 16; j++) {
            float x, y;
            unpack2(v[j], x, y);
            float q = x * y;
            float p = fmaf(x, x, y * y);
            v[j] = pack2(p, q);
        }

        // conv (p,q) pair
        {
            u64 a0 = 0ull, a1 = 0ull, a2 = 0ull, a3 = 0ull;
#pragma unroll
            for (int k = 0; k < 11; k++) {
                u64 w = w2s[k];
                fma2(a0, w, v[k]);
                fma2(a1, w, v[k + 1]);
                fma2(a2, w, v[k + 2]);
                fma2(a3, w, v[k + 3]);
            }
            ulonglong2* o = reinterpret_cast<ulonglong2*>(hPQ + r * HS + c0);
            o[0] = make_ulonglong2(a0, a1);
            o[1] = make_ulonglong2(a2, a3);
        }
    }
    __syncthreads();

    // ---- Phase 3: vertical pass (streaming, packed) + SSIM.
    //      32 cols x 4 groups of 8 rows = 128 active threads; conflict-free.
    float ssim = 0.f;
    if (tid < 128) {
        int c  = tid & 31;
        int r0 = (tid >> 5) * 8;

        u64 wr[11];
#pragma unroll
        for (int k = 0; k < 11; k++) wr[k] = w2s[k];

        u64 m12[8], epq[8];
#pragma unroll
        for (int m = 0; m < 8; m++) { m12[m] = 0ull; epq[m] = 0ull; }

#pragma unroll
        for (int j = 0; j < 18; j++) {
            int o = (r0 + j) * HS + c;
            u64 vxy = hXY[o];
            u64 vpq = hPQ[o];
#pragma unroll
            for (int m = 0; m < 8; m++) {
                int k = j - m;
                if (k >= 0 && k <= 10) {
                    fma2(m12[m], wr[k], vxy);
                    fma2(epq[m], wr[k], vpq);
                }
            }
        }
#pragma unroll
        for (int j = 0; j < 8; j++) {
            float mu1, mu2, ep, eq;
            unpack2(m12[j], mu1, mu2);
            unpack2(epq[j], ep, eq);
            float m11 = mu1 * mu1;
            float m22 = mu2 * mu2;
            float mab = mu1 * mu2;
            float s12 = eq - mab;             // sigma12
            float sss = ep - m11 - m22;       // sigma1_sq + sigma2_sq
            const float C1 = 1e-4f;   // 0.01^2
            const float C2 = 9e-4f;   // 0.03^2
            float num = (2.f * mab + C1) * (2.f * s12 + C2);
            float den = (m11 + m22 + C1) * (sss + C2);
            ssim += __fdividef(num, den);
        }
    }

    // ---- Block reduction of (l1, ssim), then one atomicAdd pair per block.
#pragma unroll
    for (int off = 16; off > 0; off >>= 1) {
        l1   += __shfl_down_sync(0xffffffffu, l1,   off);
        ssim += __shfl_down_sync(0xffffffffu, ssim, off);
    }
    int warp = tid >> 5;
    int lane = tid & 31;
    __syncthreads();            // smem must be dead before reuse
    if (lane == 0) {
        red[warp]     = l1;
        red[8 + warp] = ssim;
    }
    __syncthreads();
    if (tid == 0) {
        double a = 0.0, b = 0.0;
#pragma unroll
        for (int w = 0; w < 8; w++) { a += (double)red[w]; b += (double)red[8 + w]; }
        atomicAdd(&g_acc[0], a);
        atomicAdd(&g_acc[1], b);
    }
}

__global__ void finalize_kernel(float* __restrict__ out) {
    const double n = (double)NPIX;
    double l1 = g_acc[0] / n;
    double ss = g_acc[1] / n;
    out[0] = (float)(0.84 * l1 + (1.0 - 0.84) * (1.0 - ss));
    g_acc[0] = 0.0;   // reset for the next replay (keeps launches deterministic)
    g_acc[1] = 0.0;
}

extern "C" void kernel_launch(void* const* d_in, const int* in_sizes, int n_in,
                              void* d_out, int out_size)
{
    const float* pred = (const float*)d_in[0];
    const float* tgt  = (const float*)d_in[1];
    float* out = (float*)d_out;

    // sXY: 42*46 pairs, hXY/hPQ: 42*34 pairs each, w2s: 16 pairs (pad)
    const int smem_bytes = (IN * SXYS + 2 * IN * HS + 16) * (int)sizeof(u64); // 38528
    cudaFuncSetAttribute(ssim_l1_kernel,
                         cudaFuncAttributeMaxDynamicSharedMemorySize, smem_bytes);

    dim3 grid(IMW / TS, IMH / TS, NPLANES);   // 16 x 16 x 96
    ssim_l1_kernel<<<grid, 256, smem_bytes>>>(pred, tgt);
    finalize_kernel<<<1, 1>>>(out);
}

// round 10
// speedup vs baseline: 1.1173x; 1.1173x over previous
#include <cuda_runtime.h>

#define TS   32          // output tile (TS x TS)
#define HALO 5
#define IN   42          // TS + 2*HALO
#define INS  44          // padded smem row stride for input arrays (mult of 4)
#define IMH  512
#define IMW  512
#define NPLANES (32*3)
#define NPIX    ((long long)NPLANES * IMH * IMW)   // 25165824

// Normalized 11-tap Gaussian (sigma=1.5), compile-time so taps become FFMA-imm.
__device__ constexpr float GW[11] = {
    0.00102838f, 0.00759876f, 0.03600077f, 0.10936071f, 0.21300550f,
    0.26601172f,
    0.21300550f, 0.10936071f, 0.03600077f, 0.00759876f, 0.00102838f
};

// [0] = sum |x-y|, [1] = sum ssim_map. Zero-initialized at module load;
// finalize_kernel resets them after reading, so every replay starts from 0.
__device__ double g_acc[2] = {0.0, 0.0};

// Sliding-window conv on a 16-value register window: outputs cols j..j+3.
__device__ __forceinline__ void conv16to4(const float* __restrict__ v, float4& out)
{
    float o0 = 0.f, o1 = 0.f, o2 = 0.f, o3 = 0.f;
#pragma unroll
    for (int k = 0; k < 11; k++) {
        float w = GW[k];
        o0 += w * v[k];
        o1 += w * v[k + 1];
        o2 += w * v[k + 2];
        o3 += w * v[k + 3];
    }
    out.x = o0; out.y = o1; out.z = o2; out.w = o3;
}

__global__ __launch_bounds__(256, 4) void ssim_l1_kernel(
    const float* __restrict__ pred, const float* __restrict__ tgt)
{
    extern __shared__ float sm[];
    float* sX = sm;                   // IN*INS each (raw inputs only)
    float* sY = sX + IN * INS;
    float* hX = sY + IN * INS;        // IN*TS each (H-pass results)
    float* hY = hX + IN * TS;
    float* hP = hY + IN * TS;         // H-conv of x^2+y^2
    float* hQ = hP + IN * TS;         // H-conv of x*y

    const int tid = threadIdx.x;
    const int plane = blockIdx.z;
    const float* __restrict__ px = pred + (size_t)plane * (IMH * IMW);
    const float* __restrict__ py = tgt  + (size_t)plane * (IMH * IMW);
    const int bx0 = blockIdx.x * TS - HALO;
    const int by0 = blockIdx.y * TS - HALO;

    // ---- Phase 1: load halo tile (x, y only); fold L1 for interior pixels
    //      (each image pixel is interior of exactly one tile).
    float l1 = 0.f;
    for (int i = tid; i < IN * IN; i += 256) {
        int r = i / IN;
        int c = i - r * IN;
        int gy = by0 + r, gx = bx0 + c;
        float x = 0.f, y = 0.f;
        if ((unsigned)gy < IMH && (unsigned)gx < IMW) {
            int o = gy * IMW + gx;
            x = px[o];
            y = py[o];
        }
        int s = r * INS + c;
        sX[s] = x;
        sY[s] = y;
        if (r >= HALO && r < IN - HALO && c >= HALO && c < IN - HALO)
            l1 += fabsf(x - y);
    }
    __syncthreads();

    // ---- Phase 2: horizontal pass, p/q derived in registers.
    //      42 rows x 8 groups of 4 cols = 336 items; 8x LDS.128 per item.
    for (int i = tid; i < IN * (TS / 4); i += 256) {
        int r  = i >> 3;
        int c0 = (i & 7) * 4;
        int b  = r * INS + c0;       // 16B-aligned: r*44 and c0 mult of 4
        int ho = r * TS + c0;        // 16B-aligned

        float xv[16], yv[16];
        {
            const float4* p4 = reinterpret_cast<const float4*>(sX + b);
#pragma unroll
            for (int j = 0; j < 4; j++) {
                float4 a = p4[j];
                xv[4*j] = a.x; xv[4*j+1] = a.y; xv[4*j+2] = a.z; xv[4*j+3] = a.w;
            }
            const float4* q4 = reinterpret_cast<const float4*>(sY + b);
#pragma unroll
            for (int j = 0; j < 4; j++) {
                float4 a = q4[j];
                yv[4*j] = a.x; yv[4*j+1] = a.y; yv[4*j+2] = a.z; yv[4*j+3] = a.w;
            }
        }
        float4 o;
        conv16to4(xv, o); *reinterpret_cast<float4*>(hX + ho) = o;
        conv16to4(yv, o); *reinterpret_cast<float4*>(hY + ho) = o;
        // overwrite windows in place: xv <- x^2+y^2, yv <- x*y
#pragma unroll
        for (int j = 0; j < 16; j++) {
            float x = xv[j], y = yv[j];
            float q = x * y;
            xv[j] = x * x + y * y;
            yv[j] = q;
        }
        conv16to4(xv, o); *reinterpret_cast<float4*>(hP + ho) = o;
        conv16to4(yv, o); *reinterpret_cast<float4*>(hQ + ho) = o;
    }
    __syncthreads();

    // ---- Phase 3: vertical pass (streaming scatter-accumulate) + SSIM.
    //      32 cols x 8 groups of 4 rows = exactly 256 threads, all active.
    //      Warp lanes -> consecutive cols: conflict-free.
    float ssim = 0.f;
    {
        int c  = tid & 31;
        int r0 = (tid >> 5) * 4;
        int b  = r0 * TS + c;

        float m1[4], m2[4], ep[4], eq[4];
#pragma unroll
        for (int m = 0; m < 4; m++) { m1[m] = 0.f; m2[m] = 0.f; ep[m] = 0.f; eq[m] = 0.f; }

#pragma unroll
        for (int j = 0; j < 14; j++) {
            int o = b + j * TS;
            float vx = hX[o];
            float vy = hY[o];
            float vp = hP[o];
            float vq = hQ[o];
#pragma unroll
            for (int m = 0; m < 4; m++) {
                int k = j - m;
                if (k >= 0 && k <= 10) {
                    float w = GW[k];
                    m1[m] += w * vx;
                    m2[m] += w * vy;
                    ep[m] += w * vp;
                    eq[m] += w * vq;
                }
            }
        }
#pragma unroll
        for (int j = 0; j < 4; j++) {
            float m11 = m1[j] * m1[j];
            float m22 = m2[j] * m2[j];
            float m12 = m1[j] * m2[j];
            float s12 = eq[j] - m12;          // sigma12
            float sss = ep[j] - m11 - m22;    // sigma1_sq + sigma2_sq
            const float C1 = 1e-4f;   // 0.01^2
            const float C2 = 9e-4f;   // 0.03^2
            float num = (2.f * m12 + C1) * (2.f * s12 + C2);
            float den = (m11 + m22 + C1) * (sss + C2);
            ssim += __fdividef(num, den);
        }
    }

    // ---- Block reduction of (l1, ssim), then one atomicAdd pair per block.
#pragma unroll
    for (int off = 16; off > 0; off >>= 1) {
        l1   += __shfl_down_sync(0xffffffffu, l1,   off);
        ssim += __shfl_down_sync(0xffffffffu, ssim, off);
    }
    int warp = tid >> 5;
    int lane = tid & 31;
    __syncthreads();            // sX region must be dead before reuse
    if (lane == 0) {
        sX[warp]     = l1;
        sX[8 + warp] = ssim;
    }
    __syncthreads();
    if (tid == 0) {
        double a = 0.0, b = 0.0;
#pragma unroll
        for (int w = 0; w < 8; w++) { a += (double)sX[w]; b += (double)sX[8 + w]; }
        atomicAdd(&g_acc[0], a);
        atomicAdd(&g_acc[1], b);
    }
}

__global__ void finalize_kernel(float* __restrict__ out) {
    const double n = (double)NPIX;
    double l1 = g_acc[0] / n;
    double ss = g_acc[1] / n;
    out[0] = (float)(0.84 * l1 + (1.0 - 0.84) * (1.0 - ss));
    g_acc[0] = 0.0;   // reset for the next replay (keeps launches deterministic)
    g_acc[1] = 0.0;
}

extern "C" void kernel_launch(void* const* d_in, const int* in_sizes, int n_in,
                              void* d_out, int out_size)
{
    const float* pred = (const float*)d_in[0];
    const float* tgt  = (const float*)d_in[1];
    float* out = (float*)d_out;

    const int smem_bytes = (2 * IN * INS + 4 * IN * TS) * (int)sizeof(float); // 36288
    cudaFuncSetAttribute(ssim_l1_kernel,
                         cudaFuncAttributeMaxDynamicSharedMemorySize, smem_bytes);

    dim3 grid(IMW / TS, IMH / TS, NPLANES);   // 16 x 16 x 96
    ssim_l1_kernel<<<grid, 256, smem_bytes>>>(pred, tgt);
    finalize_kernel<<<1, 1>>>(out);
}